// round 5
// baseline (speedup 1.0000x reference)
#include <cuda_runtime.h>

#define Bb 32
#define Nn 1024
#define TDd 32
#define CINc 66
#define CSTR 80
#define EDd 10
#define OGg 128
#define OUu 64
#define COG (CINc*OGg)   // 8448
#define COU (CINc*OUu)   // 4224

typedef unsigned long long ull;

// ---------------- scratch ----------------
__device__ float g_ins [Bb*Nn*CSTR];
__device__ float g_p   [Bb*Nn*64];           // [nv1 | -nv2]
__device__ float g_q   [Bb*Nn*64];           // [nv2 |  nv1]
__device__ float g_adj [(size_t)Bb*Nn*Nn];
__device__ float g_ax  [Bb*Nn*CSTR];
__device__ float g_cand[Bb*Nn*CSTR];
__device__ float g_axc [Bb*Nn*CSTR];
__device__ float g_Wg0 [Nn*COG];
__device__ float g_Wg1 [Nn*COG];
__device__ float g_Wu0 [Nn*COU];
__device__ float g_Wu1 [Nn*COU];
__device__ float g_bg  [Nn*OGg];
__device__ float g_bu  [Nn*OUu];
__device__ float g_r   [Bb*Nn*OUu];

__device__ __forceinline__ float sigm(float v){ return 1.f/(1.f+__expf(-v)); }

__device__ __forceinline__ void ffma2(ull& d, ull a, ull b){
    asm("fma.rn.f32x2 %0, %1, %2, %0;" : "+l"(d) : "l"(a), "l"(b));
}
__device__ __forceinline__ float2 unpk(ull v){
    float2 f; asm("mov.b64 {%0, %1}, %2;" : "=f"(f.x), "=f"(f.y) : "l"(v)); return f;
}
__device__ __forceinline__ float hsum(ull v){ float2 f = unpk(v); return f.x + f.y; }

// ---------------- K1: build ins (col79=1), tiny MLPs -> p,q ----
__global__ __launch_bounds__(128) void k_prep(
    const float* __restrict__ x, const float* __restrict__ st,
    const float* __restrict__ ne0, const float* __restrict__ ne1,
    const float* __restrict__ w11, const float* __restrict__ b11,
    const float* __restrict__ w12, const float* __restrict__ b12,
    const float* __restrict__ w13, const float* __restrict__ b13,
    const float* __restrict__ w21, const float* __restrict__ b21,
    const float* __restrict__ w22, const float* __restrict__ b22,
    const float* __restrict__ w23, const float* __restrict__ b23)
{
    __shared__ float sw11[1056], sw21[1056];
    __shared__ float sb11[16], sb21[16];
    __shared__ float sw12[32], sw22[32], sb12[2], sb22[2];
    __shared__ float sw13[64], sw23[64], sb13[32], sb23[32];
    __shared__ float sv[128*67];

    int t = threadIdx.x;
    for (int i = t; i < 1056; i += 128){ sw11[i] = w11[i]; sw21[i] = w21[i]; }
    if (t < 16){ sb11[t] = b11[t]; sb21[t] = b21[t]; }
    if (t < 32){
        sw12[t] = w12[t]; sw22[t] = w22[t];
        sw13[t] = w13[t]; sw23[t] = w23[t];
        sw13[32+t] = w13[32+t]; sw23[32+t] = w23[32+t];
        sb13[t] = b13[t]; sb23[t] = b23[t];
    }
    if (t < 2){ sb12[t] = b12[t]; sb22[t] = b22[t]; }

    int idx0 = blockIdx.x*128;
    for (int e = t; e < 256; e += 128){
        int r = e >> 1, c = e & 1;
        float v = x[idx0*2 + e];
        sv[r*67 + c] = v;
        g_ins[(size_t)(idx0+r)*CSTR + c] = v;
    }
    for (int e = t; e < 128*64; e += 128){
        int r = e >> 6, c = e & 63;
        float v = st[(size_t)idx0*64 + e];
        sv[r*67 + 2 + c] = v;
        g_ins[(size_t)(idx0+r)*CSTR + 2 + c] = v;
    }
    for (int e = t; e < 128*14; e += 128){
        int r = e/14, c = 66 + e%14;
        g_ins[(size_t)(idx0+r)*CSTR + c] = (c == 79) ? 1.f : 0.f;
    }
    __syncthreads();

    int idx = idx0 + t;
    int b = idx >> 10;
    const float* vrow = &sv[t*67];

    {
        float h1[16];
        #pragma unroll
        for (int j = 0; j < 16; j++){
            float a = sb11[j];
            for (int i = 0; i < 66; i++) a += vrow[i]*sw11[i*16+j];
            h1[j] = sigm(a);
        }
        float a0 = sb12[0], a1 = sb12[1];
        #pragma unroll
        for (int j = 0; j < 16; j++){ a0 += h1[j]*sw12[j*2]; a1 += h1[j]*sw12[j*2+1]; }
        float h2a = sigm(a0), h2b = sigm(a1);
        #pragma unroll
        for (int o = 0; o < 32; o++){
            float f = sb13[o] + h2a*sw13[o] + h2b*sw13[32+o];
            float nv = tanhf(ne0[b*TDd + o]*f);
            g_p[(size_t)idx*64 + o] = nv;
            g_q[(size_t)idx*64 + 32 + o] = nv;
        }
    }
    {
        float h1[16];
        #pragma unroll
        for (int j = 0; j < 16; j++){
            float a = sb21[j];
            for (int i = 0; i < 66; i++) a += vrow[i]*sw21[i*16+j];
            h1[j] = sigm(a);
        }
        float a0 = sb22[0], a1 = sb22[1];
        #pragma unroll
        for (int j = 0; j < 16; j++){ a0 += h1[j]*sw22[j*2]; a1 += h1[j]*sw22[j*2+1]; }
        float h2a = sigm(a0), h2b = sigm(a1);
        #pragma unroll
        for (int o = 0; o < 32; o++){
            float f = sb23[o] + h2a*sw23[o] + h2b*sw23[32+o];
            float nv = tanhf(ne1[b*TDd + o]*f);
            g_p[(size_t)idx*64 + 32 + o] = -nv;
            g_q[(size_t)idx*64 + o] = nv;
        }
    }
}

// ---------------- K2: effective per-node weights ----------------
template<int CO, bool GATE>
__global__ __launch_bounds__(128) void k_wmix(const float* __restrict__ pool,
                                              const float* __restrict__ ne2)
{
    __shared__ float sne[64*EDd];
    int t = threadIdx.x;
    int row0 = blockIdx.y*64;
    for (int i = t; i < 64*EDd; i += 128) sne[i] = ne2[row0*EDd + i];
    __syncthreads();

    int col = blockIdx.x*128 + t;
    float ga[EDd], gb[EDd];
    #pragma unroll
    for (int d = 0; d < EDd; d++){
        ga[d] = pool[(size_t)(d*4+0)*CO + col] + pool[(size_t)(d*4+2)*CO + col];
        gb[d] = pool[(size_t)(d*4+1)*CO + col] + pool[(size_t)(d*4+3)*CO + col];
    }
    float* o0 = GATE ? g_Wg0 : g_Wu0;
    float* o1 = GATE ? g_Wg1 : g_Wu1;
    for (int r = 0; r < 64; r++){
        float a0 = 0.f, a1 = 0.f;
        #pragma unroll
        for (int d = 0; d < EDd; d++){ float e = sne[r*EDd+d]; a0 += e*ga[d]; a1 += e*gb[d]; }
        o0[(size_t)(row0+r)*CO + col] = a0;
        o1[(size_t)(row0+r)*CO + col] = a1;
    }
}

// merged gate+upd bias mix
__global__ void k_biases(const float* __restrict__ bg_pool, const float* __restrict__ bu_pool,
                         const float* __restrict__ ne2)
{
    int n = blockIdx.x, t = threadIdx.x;
    float ne[EDd];
    #pragma unroll
    for (int d = 0; d < EDd; d++) ne[d] = ne2[n*EDd+d];
    if (t < 128){
        float a = 0.f;
        #pragma unroll
        for (int d = 0; d < EDd; d++) a += ne[d]*bg_pool[d*OGg+t];
        g_bg[n*OGg + t] = a;
    } else {
        int o = t - 128;
        float a = 0.f;
        #pragma unroll
        for (int d = 0; d < EDd; d++) a += ne[d]*bu_pool[d*OUu+o];
        g_bu[n*OUu + o] = a;
    }
}

// ---------------- K3: adjrelu = relu(p @ q^T), K=64, k-parity FFMA2 ----
// block 256, tile 128x128, thread 8x8 (qv loaded in 2 chunks of 4 to cap regs)
#define ADJ_SP 66
__global__ __launch_bounds__(256, 1) void k_adj(){
    extern __shared__ float sm_adj[];
    float* sP = sm_adj;                 // [128][66]
    float* sQ = sm_adj + 128*ADJ_SP;    // [128][66]
    int b  = blockIdx.z;
    int r0 = blockIdx.y*128;
    int c0 = blockIdx.x*128;
    int t = threadIdx.x, tx = t & 15, ty = t >> 4;
    const float* Pb = g_p + (size_t)b*Nn*64;
    const float* Qb = g_q + (size_t)b*Nn*64;

    #pragma unroll
    for (int p = 0; p < 16; p++){
        int e = t + p*256;
        int r = e >> 5, k2 = e & 31;
        float2 v = *(const float2*)&Pb[(size_t)(r0+r)*64 + 2*k2];
        *(float2*)&sP[r*ADJ_SP + 2*k2] = v;
        float2 w = *(const float2*)&Qb[(size_t)(c0+r)*64 + 2*k2];
        *(float2*)&sQ[r*ADJ_SP + 2*k2] = w;
    }
    __syncthreads();

    ull acc[8][8] = {};
    #pragma unroll 2
    for (int k2 = 0; k2 < 32; k2++){
        int kk = 2*k2;
        ull pv[8];
        #pragma unroll
        for (int i = 0; i < 8; i++) pv[i] = *(const ull*)&sP[(ty*8+i)*ADJ_SP + kk];
        #pragma unroll
        for (int h = 0; h < 2; h++){
            ull qv[4];
            #pragma unroll
            for (int g = 0; g < 4; g++) qv[g] = *(const ull*)&sQ[(tx+16*(4*h+g))*ADJ_SP + kk];
            #pragma unroll
            for (int i = 0; i < 8; i++)
                #pragma unroll
                for (int g = 0; g < 4; g++)
                    ffma2(acc[i][4*h+g], pv[i], qv[g]);
        }
    }

    float* out = g_adj + ((size_t)b*Nn + r0)*Nn + c0;
    #pragma unroll
    for (int i = 0; i < 8; i++){
        #pragma unroll
        for (int g = 0; g < 8; g++){
            out[(size_t)(ty*8+i)*Nn + tx + 16*g] = fmaxf(hsum(acc[i][g]), 0.f);
        }
    }
}

// ---------------- K4/K7: Y = (adj @ X + X)/rowsum, k-parity FFMA2 ----
// block 256 (reg-capped for 2 CTAs/SM), tile 128 rows x 80 cols, thread 8x5.
// tx = t&15 -> cols tx*5+j (j<5); ty = t>>4 -> rows ty*8+i (i<8).
#define SPA 34
template<bool SECOND>
__global__ __launch_bounds__(256, 2) void k_spmm(){
    const float* X = SECOND ? g_cand : g_ins;
    float*       Y = SECOND ? g_axc  : g_ax;
    __shared__ float sA [128*SPA];      // [row][k] stride 34
    __shared__ float sXT[CSTR*SPA];     // [col][k] stride 34 (transposed)
    __shared__ float srs[128];
    int b = blockIdx.y;
    int row0 = blockIdx.x*128;
    int t = threadIdx.x, tx = t & 15, ty = t >> 4;
    const float* Ab = g_adj + (size_t)b*Nn*Nn;
    const float* Xb = X + (size_t)b*Nn*CSTR;

    ull acc[8][5] = {};
    for (int kt = 0; kt < 32; kt++){
        int k0 = kt*32;
        #pragma unroll
        for (int p = 0; p < 8; p++){
            int e = t + p*256;          // 2048 float2 = 128x32
            int r = e >> 4, k2 = e & 15;
            float2 v = *(const float2*)&Ab[(size_t)(row0+r)*Nn + k0 + 2*k2];
            *(float2*)&sA[r*SPA + 2*k2] = v;
        }
        #pragma unroll
        for (int p = 0; p < 10; p++){
            int e = t + p*256;          // 2560
            int k = e/80, c = e%80;
            sXT[c*SPA + k] = Xb[(size_t)(k0+k)*CSTR + c];
        }
        __syncthreads();
        #pragma unroll 4
        for (int k2 = 0; k2 < 16; k2++){
            int kk = 2*k2;
            ull av[8], xv[5];
            #pragma unroll
            for (int i = 0; i < 8; i++) av[i] = *(const ull*)&sA[(ty*8+i)*SPA + kk];
            #pragma unroll
            for (int j = 0; j < 5; j++) xv[j] = *(const ull*)&sXT[(tx*5+j)*SPA + kk];
            #pragma unroll
            for (int i = 0; i < 8; i++)
                #pragma unroll
                for (int j = 0; j < 5; j++)
                    ffma2(acc[i][j], av[i], xv[j]);
        }
        __syncthreads();
    }

    // ones-col 79 = (tx==15, j==4): acc = rowsum - 1
    if (tx == 15){
        #pragma unroll
        for (int i = 0; i < 8; i++) srs[ty*8 + i] = hsum(acc[i][4]) + 1.f;
    }
    __syncthreads();

    #pragma unroll
    for (int i = 0; i < 8; i++){
        int r = row0 + ty*8 + i;
        float inv = 1.f/srs[ty*8 + i];
        #pragma unroll
        for (int j = 0; j < 5; j++){
            int c = tx*5 + j;
            Y[((size_t)b*Nn + r)*CSTR + c] = (hsum(acc[i][j]) + Xb[(size_t)r*CSTR + c])*inv;
        }
    }
}

// ---------------- K5: gate node-GEMM -> z,r; builds cand (col79=1) ----------------
__global__ __launch_bounds__(128) void k_gate(const float* __restrict__ x,
                                              const float* __restrict__ state)
{
    extern __shared__ float sm[];
    float* sW0 = sm;
    float* sW1 = sm + COG;
    float* sX  = sm + 2*COG;
    float* sAX = sm + 2*COG + 2112;
    int n = blockIdx.x, t = threadIdx.x;
    int bg = t >> 5, og = t & 31;

    {
        float4* d0 = (float4*)sW0; const float4* s0 = (const float4*)(g_Wg0 + (size_t)n*COG);
        float4* d1 = (float4*)sW1; const float4* s1 = (const float4*)(g_Wg1 + (size_t)n*COG);
        for (int e = t; e < COG/4; e += 128){ d0[e] = s0[e]; d1[e] = s1[e]; }
    }
    for (int e = t; e < 32*66; e += 128){
        int bi = e/66, i = e%66;
        sX [e] = g_ins[((size_t)bi*Nn + n)*CSTR + i];
        sAX[e] = g_ax [((size_t)bi*Nn + n)*CSTR + i];
    }
    __syncthreads();

    float4 acc[8] = {};
    #pragma unroll 2
    for (int i = 0; i < 66; i++){
        float4 w0 = ((const float4*)sW0)[i*32 + og];
        float4 w1 = ((const float4*)sW1)[i*32 + og];
        #pragma unroll
        for (int bb = 0; bb < 8; bb++){
            int bi = bg*8 + bb;
            float xv = sX[bi*66 + i], av = sAX[bi*66 + i];
            acc[bb].x += xv*w0.x + av*w1.x;
            acc[bb].y += xv*w0.y + av*w1.y;
            acc[bb].z += xv*w0.z + av*w1.z;
            acc[bb].w += xv*w0.w + av*w1.w;
        }
    }
    float4 bias = *(const float4*)(g_bg + n*OGg + og*4);
    int o0 = og*4;
    #pragma unroll
    for (int bb = 0; bb < 8; bb++){
        int bi = bg*8 + bb;
        size_t bn = (size_t)bi*Nn + n;
        float vals[4] = { acc[bb].x + bias.x, acc[bb].y + bias.y,
                          acc[bb].z + bias.z, acc[bb].w + bias.w };
        #pragma unroll
        for (int c = 0; c < 4; c++){
            float zz = sigm(vals[c]);
            int o = o0 + c;
            if (o < 64) g_cand[bn*CSTR + 2 + o] = zz * state[bn*64 + o];
            else        g_r  [bn*64 + (o - 64)] = zz;
        }
    }
    if (og == 0){
        #pragma unroll
        for (int bb = 0; bb < 8; bb++){
            size_t bn = (size_t)(bg*8 + bb)*Nn + n;
            g_cand[bn*CSTR + 0] = x[bn*2 + 0];
            g_cand[bn*CSTR + 1] = x[bn*2 + 1];
            #pragma unroll
            for (int c = 66; c < 80; c++) g_cand[bn*CSTR + c] = (c == 79) ? 1.f : 0.f;
        }
    }
}

// ---------------- K8: upd node-GEMM -> hc; final out ----------------
__global__ __launch_bounds__(128) void k_upd(const float* __restrict__ state,
                                             float* __restrict__ out)
{
    extern __shared__ float sm[];
    float* sW0 = sm;
    float* sW1 = sm + COU;
    float* sX  = sm + 2*COU;
    float* sAX = sm + 2*COU + 2112;
    int n = blockIdx.x, t = threadIdx.x;
    int bg = t >> 5, og = t & 31;

    {
        float4* d0 = (float4*)sW0; const float4* s0 = (const float4*)(g_Wu0 + (size_t)n*COU);
        float4* d1 = (float4*)sW1; const float4* s1 = (const float4*)(g_Wu1 + (size_t)n*COU);
        for (int e = t; e < COU/4; e += 128){ d0[e] = s0[e]; d1[e] = s1[e]; }
    }
    for (int e = t; e < 32*66; e += 128){
        int bi = e/66, i = e%66;
        sX [e] = g_cand[((size_t)bi*Nn + n)*CSTR + i];
        sAX[e] = g_axc [((size_t)bi*Nn + n)*CSTR + i];
    }
    __syncthreads();

    float2 acc[8] = {};
    #pragma unroll 2
    for (int i = 0; i < 66; i++){
        float2 w0 = ((const float2*)sW0)[i*32 + og];
        float2 w1 = ((const float2*)sW1)[i*32 + og];
        #pragma unroll
        for (int bb = 0; bb < 8; bb++){
            int bi = bg*8 + bb;
            float xv = sX[bi*66 + i], av = sAX[bi*66 + i];
            acc[bb].x += xv*w0.x + av*w1.x;
            acc[bb].y += xv*w0.y + av*w1.y;
        }
    }
    float2 bias = ((const float2*)(g_bu + n*OUu))[og];
    #pragma unroll
    for (int bb = 0; bb < 8; bb++){
        int bi = bg*8 + bb;
        size_t bn = (size_t)bi*Nn + n;
        #pragma unroll
        for (int c = 0; c < 2; c++){
            int o = og*2 + c;
            float hc = tanhf((c ? acc[bb].y + bias.y : acc[bb].x + bias.x));
            float rr = g_r[bn*64 + o];
            float sv = state[bn*64 + o];
            out[bn*64 + o] = rr*sv + (1.f - rr)*hc;
        }
    }
}

// ---------------- launcher ----------------
extern "C" void kernel_launch(void* const* d_in, const int* in_sizes, int n_in,
                              void* d_out, int out_size)
{
    const float* x      = (const float*)d_in[0];
    const float* state  = (const float*)d_in[1];
    const float* ne0    = (const float*)d_in[2];
    const float* ne1    = (const float*)d_in[3];
    const float* ne2    = (const float*)d_in[4];
    const float* f1w1   = (const float*)d_in[5];
    const float* f1b1   = (const float*)d_in[6];
    const float* f1w2   = (const float*)d_in[7];
    const float* f1b2   = (const float*)d_in[8];
    const float* f1w3   = (const float*)d_in[9];
    const float* f1b3   = (const float*)d_in[10];
    const float* f2w1   = (const float*)d_in[11];
    const float* f2b1   = (const float*)d_in[12];
    const float* f2w2   = (const float*)d_in[13];
    const float* f2b2   = (const float*)d_in[14];
    const float* f2w3   = (const float*)d_in[15];
    const float* f2b3   = (const float*)d_in[16];
    const float* gate_w = (const float*)d_in[17];
    const float* gate_b = (const float*)d_in[18];
    const float* upd_w  = (const float*)d_in[19];
    const float* upd_b  = (const float*)d_in[20];
    float* out = (float*)d_out;

    cudaFuncSetAttribute(k_gate, cudaFuncAttributeMaxDynamicSharedMemorySize, (2*COG + 2*2112)*4);
    cudaFuncSetAttribute(k_upd,  cudaFuncAttributeMaxDynamicSharedMemorySize, (2*COU + 2*2112)*4);
    cudaFuncSetAttribute(k_adj,  cudaFuncAttributeMaxDynamicSharedMemorySize, 2*128*ADJ_SP*4);

    // Order chosen so launch #4 (the one ncu captures) is k_spmm<false>.
    k_prep<<<256, 128>>>(x, state, ne0, ne1,
                         f1w1, f1b1, f1w2, f1b2, f1w3, f1b3,
                         f2w1, f2b1, f2w2, f2b2, f2w3, f2b3);
    k_adj<<<dim3(8, 8, Bb), 256, 2*128*ADJ_SP*4>>>();
    k_wmix<COG, true ><<<dim3(COG/128, Nn/64), 128>>>(gate_w, ne2);
    k_spmm<false><<<dim3(8, Bb), 256>>>();
    k_wmix<COU, false><<<dim3(COU/128, Nn/64), 128>>>(upd_w,  ne2);
    k_biases<<<Nn, 192>>>(gate_b, upd_b, ne2);
    k_gate<<<Nn, 128, (2*COG + 2*2112)*4>>>(x, state);
    k_spmm<true><<<dim3(8, Bb), 256>>>();
    k_upd<<<Nn, 128, (2*COU + 2*2112)*4>>>(state, out);
}

// round 8
// speedup vs baseline: 1.5695x; 1.5695x over previous
#include <cuda_runtime.h>
#include <cstdint>

#define Bb 32
#define Nn 1024
#define TDd 32
#define CINc 66
#define CSTR 80
#define EDd 10
#define OGg 128
#define OUu 64
#define COG (CINc*OGg)   // 8448
#define COU (CINc*OUu)   // 4224

typedef unsigned long long ull;

// ---------------- scratch ----------------
__device__ float g_ins [Bb*Nn*CSTR];
__device__ float g_p   [Bb*Nn*64];           // [nv1 | -nv2]
__device__ float g_q   [Bb*Nn*64];           // [nv2 |  nv1]
__device__ float g_adj [(size_t)Bb*Nn*Nn];
__device__ float g_ax  [Bb*Nn*CSTR];
__device__ float g_cand[Bb*Nn*CSTR];
__device__ float g_axc [Bb*Nn*CSTR];
__device__ float g_Wg0 [Nn*COG];
__device__ float g_Wg1 [Nn*COG];
__device__ float g_Wu0 [Nn*COU];
__device__ float g_Wu1 [Nn*COU];
__device__ float g_bg  [Nn*OGg];
__device__ float g_bu  [Nn*OUu];
__device__ float g_r   [Bb*Nn*OUu];

__device__ __forceinline__ float sigm(float v){ return 1.f/(1.f+__expf(-v)); }

// ---- tf32 mma.sync helpers (base-PTX, no 'a'-features) ----
__device__ __forceinline__ uint32_t tf32u(float v){
    uint32_t o; asm("cvt.rna.tf32.f32 %0, %1;" : "=r"(o) : "f"(v)); return o;
}
__device__ __forceinline__ void mma8(float* c, const uint32_t* a, const uint32_t* b){
    asm volatile("mma.sync.aligned.m16n8k8.row.col.f32.tf32.tf32.f32 "
        "{%0,%1,%2,%3}, {%4,%5,%6,%7}, {%8,%9}, {%0,%1,%2,%3};"
        : "+f"(c[0]), "+f"(c[1]), "+f"(c[2]), "+f"(c[3])
        : "r"(a[0]), "r"(a[1]), "r"(a[2]), "r"(a[3]), "r"(b[0]), "r"(b[1]));
}

// ---------------- K1: build ins (col79=1), tiny MLPs -> p,q ----
__global__ __launch_bounds__(128) void k_prep(
    const float* __restrict__ x, const float* __restrict__ st,
    const float* __restrict__ ne0, const float* __restrict__ ne1,
    const float* __restrict__ w11, const float* __restrict__ b11,
    const float* __restrict__ w12, const float* __restrict__ b12,
    const float* __restrict__ w13, const float* __restrict__ b13,
    const float* __restrict__ w21, const float* __restrict__ b21,
    const float* __restrict__ w22, const float* __restrict__ b22,
    const float* __restrict__ w23, const float* __restrict__ b23)
{
    __shared__ float sw11[1056], sw21[1056];
    __shared__ float sb11[16], sb21[16];
    __shared__ float sw12[32], sw22[32], sb12[2], sb22[2];
    __shared__ float sw13[64], sw23[64], sb13[32], sb23[32];
    __shared__ float sv[128*67];

    int t = threadIdx.x;
    for (int i = t; i < 1056; i += 128){ sw11[i] = w11[i]; sw21[i] = w21[i]; }
    if (t < 16){ sb11[t] = b11[t]; sb21[t] = b21[t]; }
    if (t < 32){
        sw12[t] = w12[t]; sw22[t] = w22[t];
        sw13[t] = w13[t]; sw23[t] = w23[t];
        sw13[32+t] = w13[32+t]; sw23[32+t] = w23[32+t];
        sb13[t] = b13[t]; sb23[t] = b23[t];
    }
    if (t < 2){ sb12[t] = b12[t]; sb22[t] = b22[t]; }

    int idx0 = blockIdx.x*128;
    for (int e = t; e < 256; e += 128){
        int r = e >> 1, c = e & 1;
        float v = x[idx0*2 + e];
        sv[r*67 + c] = v;
        g_ins[(size_t)(idx0+r)*CSTR + c] = v;
    }
    for (int e = t; e < 128*64; e += 128){
        int r = e >> 6, c = e & 63;
        float v = st[(size_t)idx0*64 + e];
        sv[r*67 + 2 + c] = v;
        g_ins[(size_t)(idx0+r)*CSTR + 2 + c] = v;
    }
    for (int e = t; e < 128*14; e += 128){
        int r = e/14, c = 66 + e%14;
        g_ins[(size_t)(idx0+r)*CSTR + c] = (c == 79) ? 1.f : 0.f;
    }
    __syncthreads();

    int idx = idx0 + t;
    int b = idx >> 10;
    const float* vrow = &sv[t*67];

    {
        float h1[16];
        #pragma unroll
        for (int j = 0; j < 16; j++){
            float a = sb11[j];
            for (int i = 0; i < 66; i++) a += vrow[i]*sw11[i*16+j];
            h1[j] = sigm(a);
        }
        float a0 = sb12[0], a1 = sb12[1];
        #pragma unroll
        for (int j = 0; j < 16; j++){ a0 += h1[j]*sw12[j*2]; a1 += h1[j]*sw12[j*2+1]; }
        float h2a = sigm(a0), h2b = sigm(a1);
        #pragma unroll
        for (int o = 0; o < 32; o++){
            float f = sb13[o] + h2a*sw13[o] + h2b*sw13[32+o];
            float nv = tanhf(ne0[b*TDd + o]*f);
            g_p[(size_t)idx*64 + o] = nv;
            g_q[(size_t)idx*64 + 32 + o] = nv;
        }
    }
    {
        float h1[16];
        #pragma unroll
        for (int j = 0; j < 16; j++){
            float a = sb21[j];
            for (int i = 0; i < 66; i++) a += vrow[i]*sw21[i*16+j];
            h1[j] = sigm(a);
        }
        float a0 = sb22[0], a1 = sb22[1];
        #pragma unroll
        for (int j = 0; j < 16; j++){ a0 += h1[j]*sw22[j*2]; a1 += h1[j]*sw22[j*2+1]; }
        float h2a = sigm(a0), h2b = sigm(a1);
        #pragma unroll
        for (int o = 0; o < 32; o++){
            float f = sb23[o] + h2a*sw23[o] + h2b*sw23[32+o];
            float nv = tanhf(ne1[b*TDd + o]*f);
            g_p[(size_t)idx*64 + 32 + o] = -nv;
            g_q[(size_t)idx*64 + o] = nv;
        }
    }
}

// ---------------- K2: effective per-node weights ----------------
template<int CO, bool GATE>
__global__ __launch_bounds__(128) void k_wmix(const float* __restrict__ pool,
                                              const float* __restrict__ ne2)
{
    __shared__ float sne[64*EDd];
    int t = threadIdx.x;
    int row0 = blockIdx.y*64;
    for (int i = t; i < 64*EDd; i += 128) sne[i] = ne2[row0*EDd + i];
    __syncthreads();

    int col = blockIdx.x*128 + t;
    float ga[EDd], gb[EDd];
    #pragma unroll
    for (int d = 0; d < EDd; d++){
        ga[d] = pool[(size_t)(d*4+0)*CO + col] + pool[(size_t)(d*4+2)*CO + col];
        gb[d] = pool[(size_t)(d*4+1)*CO + col] + pool[(size_t)(d*4+3)*CO + col];
    }
    float* o0 = GATE ? g_Wg0 : g_Wu0;
    float* o1 = GATE ? g_Wg1 : g_Wu1;
    for (int r = 0; r < 64; r++){
        float a0 = 0.f, a1 = 0.f;
        #pragma unroll
        for (int d = 0; d < EDd; d++){ float e = sne[r*EDd+d]; a0 += e*ga[d]; a1 += e*gb[d]; }
        o0[(size_t)(row0+r)*CO + col] = a0;
        o1[(size_t)(row0+r)*CO + col] = a1;
    }
}

__global__ void k_biases(const float* __restrict__ bg_pool, const float* __restrict__ bu_pool,
                         const float* __restrict__ ne2)
{
    int n = blockIdx.x, t = threadIdx.x;
    float ne[EDd];
    #pragma unroll
    for (int d = 0; d < EDd; d++) ne[d] = ne2[n*EDd+d];
    if (t < 128){
        float a = 0.f;
        #pragma unroll
        for (int d = 0; d < EDd; d++) a += ne[d]*bg_pool[d*OGg+t];
        g_bg[n*OGg + t] = a;
    } else {
        int o = t - 128;
        float a = 0.f;
        #pragma unroll
        for (int d = 0; d < EDd; d++) a += ne[d]*bu_pool[d*OUu+o];
        g_bu[n*OUu + o] = a;
    }
}

// ---------------- K3: adjrelu = relu(p @ q^T) via split-tf32 mma.sync ----------------
// grid (8 col, 8 row, Bb), block 256. Tile 128x128, K=64 in 2 chunks of 32.
// Warp: wg = w>>1 (rows wg*32, two m16 tiles), cg = w&1 (cols cg*64, eight n8 tiles).
// smem (dynamic): sPh/sPl [128][36], sQh/sQl [128][36]  (4 x 18432 B = 73728 B)
__global__ __launch_bounds__(256) void k_adj(){
    extern __shared__ uint32_t smadj[];
    uint32_t* sPh = smadj;
    uint32_t* sPl = smadj + 128*36;
    uint32_t* sQh = smadj + 2*128*36;
    uint32_t* sQl = smadj + 3*128*36;
    int t = threadIdx.x, w = t >> 5, lane = t & 31;
    int wg = w >> 1, cg = w & 1;
    int quad = lane >> 2, tig = lane & 3;
    int b  = blockIdx.z;
    int r0 = blockIdx.y*128;
    int c0 = blockIdx.x*128;
    const float* Pb = g_p + (size_t)b*Nn*64;
    const float* Qb = g_q + (size_t)b*Nn*64;

    float acc[2][8][4] = {};

    for (int kc = 0; kc < 2; kc++){
        int k0 = kc*32;
        if (kc) __syncthreads();
        #pragma unroll
        for (int p = 0; p < 4; p++){
            int e = t + p*256;          // 1024: r = e>>3, m = e&7
            int r = e >> 3, m = e & 7;
            float4 v = *(const float4*)&Pb[(size_t)(r0+r)*64 + k0 + m*4];
            uint4 h, l;
            h.x = tf32u(v.x); l.x = tf32u(v.x - __uint_as_float(h.x));
            h.y = tf32u(v.y); l.y = tf32u(v.y - __uint_as_float(h.y));
            h.z = tf32u(v.z); l.z = tf32u(v.z - __uint_as_float(h.z));
            h.w = tf32u(v.w); l.w = tf32u(v.w - __uint_as_float(h.w));
            *(uint4*)&sPh[r*36 + m*4] = h;
            *(uint4*)&sPl[r*36 + m*4] = l;
            float4 q = *(const float4*)&Qb[(size_t)(c0+r)*64 + k0 + m*4];
            h.x = tf32u(q.x); l.x = tf32u(q.x - __uint_as_float(h.x));
            h.y = tf32u(q.y); l.y = tf32u(q.y - __uint_as_float(h.y));
            h.z = tf32u(q.z); l.z = tf32u(q.z - __uint_as_float(h.z));
            h.w = tf32u(q.w); l.w = tf32u(q.w - __uint_as_float(h.w));
            *(uint4*)&sQh[r*36 + m*4] = h;
            *(uint4*)&sQl[r*36 + m*4] = l;
        }
        __syncthreads();

        #pragma unroll
        for (int k8 = 0; k8 < 4; k8++){
            int kk = k8*8;
            uint32_t ah[2][4], al[2][4];
            #pragma unroll
            for (int mi = 0; mi < 2; mi++){
                int R = wg*32 + mi*16 + quad;
                ah[mi][0] = sPh[(R  )*36 + kk + tig];
                ah[mi][1] = sPh[(R+8)*36 + kk + tig];
                ah[mi][2] = sPh[(R  )*36 + kk + tig + 4];
                ah[mi][3] = sPh[(R+8)*36 + kk + tig + 4];
                al[mi][0] = sPl[(R  )*36 + kk + tig];
                al[mi][1] = sPl[(R+8)*36 + kk + tig];
                al[mi][2] = sPl[(R  )*36 + kk + tig + 4];
                al[mi][3] = sPl[(R+8)*36 + kk + tig + 4];
            }
            #pragma unroll
            for (int nj = 0; nj < 8; nj++){
                int n = cg*64 + nj*8 + quad;
                uint32_t bh[2], bl[2];
                bh[0] = sQh[n*36 + kk + tig];
                bh[1] = sQh[n*36 + kk + tig + 4];
                bl[0] = sQl[n*36 + kk + tig];
                bl[1] = sQl[n*36 + kk + tig + 4];
                mma8(acc[0][nj], ah[0], bh);
                mma8(acc[1][nj], ah[1], bh);
                mma8(acc[0][nj], ah[0], bl);
                mma8(acc[1][nj], ah[1], bl);
                mma8(acc[0][nj], al[0], bh);
                mma8(acc[1][nj], al[1], bh);
            }
        }
    }

    #pragma unroll
    for (int mi = 0; mi < 2; mi++){
        #pragma unroll
        for (int rp = 0; rp < 2; rp++){
            int row = r0 + wg*32 + mi*16 + quad + rp*8;
            float* orow = g_adj + ((size_t)b*Nn + row)*Nn + c0 + cg*64;
            #pragma unroll
            for (int nj = 0; nj < 8; nj++){
                float2 v;
                v.x = fmaxf(acc[mi][nj][rp*2+0], 0.f);
                v.y = fmaxf(acc[mi][nj][rp*2+1], 0.f);
                *(float2*)&orow[nj*8 + 2*tig] = v;
            }
        }
    }
}

// ---------------- K4/K7: Y = (adj @ X + X)/rowsum via tf32 mma.sync ----------------
// grid (8, Bb), block 256. Tile 128 x 80, K=1024 in 32 chunks of 32.
// Warp: wg = w>>1 (rows wg*32, two m16 tiles), cg = w&1 (cols cg*40, five n8 tiles).
template<bool SECOND>
__global__ __launch_bounds__(256) void k_spmm(){
    const float* X = SECOND ? g_cand : g_ins;
    float*       Y = SECOND ? g_axc  : g_ax;
    __shared__ uint32_t sA[128*36];     // [r][k] stride 36
    __shared__ uint32_t sX[32*88];      // [k][n] stride 88
    __shared__ float srs[128];
    int t = threadIdx.x, w = t >> 5, lane = t & 31;
    int wg = w >> 1, cg = w & 1;
    int quad = lane >> 2, tig = lane & 3;
    int b = blockIdx.y;
    int row0 = blockIdx.x*128;
    const float* Ab = g_adj + (size_t)b*Nn*Nn + (size_t)row0*Nn;
    const float* Xb = X + (size_t)b*Nn*CSTR;

    float acc[2][5][4] = {};

    for (int kt = 0; kt < 32; kt++){
        if (kt) __syncthreads();
        // A: 128x32 tf32
        #pragma unroll
        for (int p = 0; p < 4; p++){
            int e = t + p*256;          // 1024: r = e>>3, m = e&7
            int r = e >> 3, m = e & 7;
            float4 v = *(const float4*)&Ab[(size_t)r*Nn + kt*32 + m*4];
            uint4 u;
            u.x = tf32u(v.x); u.y = tf32u(v.y); u.z = tf32u(v.z); u.w = tf32u(v.w);
            *(uint4*)&sA[r*36 + m*4] = u;
        }
        // X chunk: 32(k) x 80(n) tf32
        #pragma unroll
        for (int p = 0; p < 10; p++){
            int e = t + p*256;          // 2560
            int k = e/80, n = e%80;
            sX[k*88 + n] = tf32u(Xb[(size_t)(kt*32 + k)*CSTR + n]);
        }
        __syncthreads();

        #pragma unroll
        for (int k8 = 0; k8 < 4; k8++){
            int kk = k8*8;
            uint32_t a[2][4];
            #pragma unroll
            for (int mi = 0; mi < 2; mi++){
                int R = wg*32 + mi*16 + quad;
                a[mi][0] = sA[(R  )*36 + kk + tig];
                a[mi][1] = sA[(R+8)*36 + kk + tig];
                a[mi][2] = sA[(R  )*36 + kk + tig + 4];
                a[mi][3] = sA[(R+8)*36 + kk + tig + 4];
            }
            #pragma unroll
            for (int nj = 0; nj < 5; nj++){
                int n = cg*40 + nj*8 + quad;
                uint32_t bf[2];
                bf[0] = sX[(kk + tig    )*88 + n];
                bf[1] = sX[(kk + tig + 4)*88 + n];
                mma8(acc[0][nj], a[0], bf);
                mma8(acc[1][nj], a[1], bf);
            }
        }
    }

    // rowsum from ones-col 79: cg==1, nj==4, tig==3, c1/c3
    if (cg == 1 && tig == 3){
        #pragma unroll
        for (int mi = 0; mi < 2; mi++){
            srs[wg*32 + mi*16 + quad    ] = acc[mi][4][1] + 1.f;
            srs[wg*32 + mi*16 + quad + 8] = acc[mi][4][3] + 1.f;
        }
    }
    __syncthreads();

    #pragma unroll
    for (int mi = 0; mi < 2; mi++){
        #pragma unroll
        for (int rp = 0; rp < 2; rp++){
            int lr  = wg*32 + mi*16 + quad + rp*8;
            int row = row0 + lr;
            float inv = 1.f/srs[lr];
            const float* xr = Xb + (size_t)row*CSTR;
            float* yr = Y + ((size_t)b*Nn + row)*CSTR;
            #pragma unroll
            for (int nj = 0; nj < 5; nj++){
                int col = cg*40 + nj*8 + 2*tig;
                float2 xv = *(const float2*)&xr[col];
                float2 o;
                o.x = (acc[mi][nj][rp*2+0] + xv.x)*inv;
                o.y = (acc[mi][nj][rp*2+1] + xv.y)*inv;
                *(float2*)&yr[col] = o;
            }
        }
    }
}

// ---------------- K5: gate node-GEMM -> z,r; builds cand (col79=1) ----------------
__global__ __launch_bounds__(128) void k_gate(const float* __restrict__ x,
                                              const float* __restrict__ state)
{
    extern __shared__ float sm[];
    float* sW0 = sm;
    float* sW1 = sm + COG;
    float* sX  = sm + 2*COG;
    float* sAX = sm + 2*COG + 2112;
    int n = blockIdx.x, t = threadIdx.x;
    int bg = t >> 5, og = t & 31;

    {
        float4* d0 = (float4*)sW0; const float4* s0 = (const float4*)(g_Wg0 + (size_t)n*COG);
        float4* d1 = (float4*)sW1; const float4* s1 = (const float4*)(g_Wg1 + (size_t)n*COG);
        for (int e = t; e < COG/4; e += 128){ d0[e] = s0[e]; d1[e] = s1[e]; }
    }
    for (int e = t; e < 32*66; e += 128){
        int bi = e/66, i = e%66;
        sX [e] = g_ins[((size_t)bi*Nn + n)*CSTR + i];
        sAX[e] = g_ax [((size_t)bi*Nn + n)*CSTR + i];
    }
    __syncthreads();

    float4 acc[8] = {};
    #pragma unroll 2
    for (int i = 0; i < 66; i++){
        float4 w0 = ((const float4*)sW0)[i*32 + og];
        float4 w1 = ((const float4*)sW1)[i*32 + og];
        #pragma unroll
        for (int bb = 0; bb < 8; bb++){
            int bi = bg*8 + bb;
            float xv = sX[bi*66 + i], av = sAX[bi*66 + i];
            acc[bb].x += xv*w0.x + av*w1.x;
            acc[bb].y += xv*w0.y + av*w1.y;
            acc[bb].z += xv*w0.z + av*w1.z;
            acc[bb].w += xv*w0.w + av*w1.w;
        }
    }
    float4 bias = *(const float4*)(g_bg + n*OGg + og*4);
    int o0 = og*4;
    #pragma unroll
    for (int bb = 0; bb < 8; bb++){
        int bi = bg*8 + bb;
        size_t bn = (size_t)bi*Nn + n;
        float vals[4] = { acc[bb].x + bias.x, acc[bb].y + bias.y,
                          acc[bb].z + bias.z, acc[bb].w + bias.w };
        #pragma unroll
        for (int c = 0; c < 4; c++){
            float zz = sigm(vals[c]);
            int o = o0 + c;
            if (o < 64) g_cand[bn*CSTR + 2 + o] = zz * state[bn*64 + o];
            else        g_r  [bn*64 + (o - 64)] = zz;
        }
    }
    if (og == 0){
        #pragma unroll
        for (int bb = 0; bb < 8; bb++){
            size_t bn = (size_t)(bg*8 + bb)*Nn + n;
            g_cand[bn*CSTR + 0] = x[bn*2 + 0];
            g_cand[bn*CSTR + 1] = x[bn*2 + 1];
            #pragma unroll
            for (int c = 66; c < 80; c++) g_cand[bn*CSTR + c] = (c == 79) ? 1.f : 0.f;
        }
    }
}

// ---------------- K8: upd node-GEMM -> hc; final out ----------------
__global__ __launch_bounds__(128) void k_upd(const float* __restrict__ state,
                                             float* __restrict__ out)
{
    extern __shared__ float sm[];
    float* sW0 = sm;
    float* sW1 = sm + COU;
    float* sX  = sm + 2*COU;
    float* sAX = sm + 2*COU + 2112;
    int n = blockIdx.x, t = threadIdx.x;
    int bg = t >> 5, og = t & 31;

    {
        float4* d0 = (float4*)sW0; const float4* s0 = (const float4*)(g_Wu0 + (size_t)n*COU);
        float4* d1 = (float4*)sW1; const float4* s1 = (const float4*)(g_Wu1 + (size_t)n*COU);
        for (int e = t; e < COU/4; e += 128){ d0[e] = s0[e]; d1[e] = s1[e]; }
    }
    for (int e = t; e < 32*66; e += 128){
        int bi = e/66, i = e%66;
        sX [e] = g_cand[((size_t)bi*Nn + n)*CSTR + i];
        sAX[e] = g_axc [((size_t)bi*Nn + n)*CSTR + i];
    }
    __syncthreads();

    float2 acc[8] = {};
    #pragma unroll 2
    for (int i = 0; i < 66; i++){
        float2 w0 = ((const float2*)sW0)[i*32 + og];
        float2 w1 = ((const float2*)sW1)[i*32 + og];
        #pragma unroll
        for (int bb = 0; bb < 8; bb++){
            int bi = bg*8 + bb;
            float xv = sX[bi*66 + i], av = sAX[bi*66 + i];
            acc[bb].x += xv*w0.x + av*w1.x;
            acc[bb].y += xv*w0.y + av*w1.y;
        }
    }
    float2 bias = ((const float2*)(g_bu + n*OUu))[og];
    #pragma unroll
    for (int bb = 0; bb < 8; bb++){
        int bi = bg*8 + bb;
        size_t bn = (size_t)bi*Nn + n;
        #pragma unroll
        for (int c = 0; c < 2; c++){
            int o = og*2 + c;
            float hc = tanhf((c ? acc[bb].y + bias.y : acc[bb].x + bias.x));
            float rr = g_r[bn*64 + o];
            float sv = state[bn*64 + o];
            out[bn*64 + o] = rr*sv + (1.f - rr)*hc;
        }
    }
}

// ---------------- launcher ----------------
extern "C" void kernel_launch(void* const* d_in, const int* in_sizes, int n_in,
                              void* d_out, int out_size)
{
    const float* x      = (const float*)d_in[0];
    const float* state  = (const float*)d_in[1];
    const float* ne0    = (const float*)d_in[2];
    const float* ne1    = (const float*)d_in[3];
    const float* ne2    = (const float*)d_in[4];
    const float* f1w1   = (const float*)d_in[5];
    const float* f1b1   = (const float*)d_in[6];
    const float* f1w2   = (const float*)d_in[7];
    const float* f1b2   = (const float*)d_in[8];
    const float* f1w3   = (const float*)d_in[9];
    const float* f1b3   = (const float*)d_in[10];
    const float* f2w1   = (const float*)d_in[11];
    const float* f2b1   = (const float*)d_in[12];
    const float* f2w2   = (const float*)d_in[13];
    const float* f2b2   = (const float*)d_in[14];
    const float* f2w3   = (const float*)d_in[15];
    const float* f2b3   = (const float*)d_in[16];
    const float* gate_w = (const float*)d_in[17];
    const float* gate_b = (const float*)d_in[18];
    const float* upd_w  = (const float*)d_in[19];
    const float* upd_b  = (const float*)d_in[20];
    float* out = (float*)d_out;

    const int ADJ_SMEM = 4*128*36*4;   // 73728 B
    cudaFuncSetAttribute(k_adj,  cudaFuncAttributeMaxDynamicSharedMemorySize, ADJ_SMEM);
    cudaFuncSetAttribute(k_gate, cudaFuncAttributeMaxDynamicSharedMemorySize, (2*COG + 2*2112)*4);
    cudaFuncSetAttribute(k_upd,  cudaFuncAttributeMaxDynamicSharedMemorySize, (2*COU + 2*2112)*4);

    // Order chosen so launch #4 (the one ncu captures) is k_spmm<false>.
    k_prep<<<256, 128>>>(x, state, ne0, ne1,
                         f1w1, f1b1, f1w2, f1b2, f1w3, f1b3,
                         f2w1, f2b1, f2w2, f2b2, f2w3, f2b3);
    k_adj<<<dim3(8, 8, Bb), 256, ADJ_SMEM>>>();
    k_wmix<COG, true ><<<dim3(COG/128, Nn/64), 128>>>(gate_w, ne2);
    k_spmm<false><<<dim3(8, Bb), 256>>>();
    k_wmix<COU, false><<<dim3(COU/128, Nn/64), 128>>>(upd_w,  ne2);
    k_biases<<<Nn, 192>>>(gate_b, upd_b, ne2);
    k_gate<<<Nn, 128, (2*COG + 2*2112)*4>>>(x, state);
    k_spmm<true><<<dim3(8, Bb), 256>>>();
    k_upd<<<Nn, 128, (2*COU + 2*2112)*4>>>(state, out);
}

// round 11
// speedup vs baseline: 1.7764x; 1.1318x over previous
#include <cuda_runtime.h>
#include <cstdint>

#define Bb 32
#define Nn 1024
#define TDd 32
#define CINc 66
#define CSTR 80
#define EDd 10
#define OGg 128
#define OUu 64
#define COG (CINc*OGg)   // 8448
#define COU (CINc*OUu)   // 4224

typedef unsigned long long ull;

// ---------------- scratch ----------------
__device__ float g_ins [Bb*Nn*CSTR];
__device__ float g_p   [Bb*Nn*64];           // [nv1 | -nv2]
__device__ float g_q   [Bb*Nn*64];           // [nv2 |  nv1]
__device__ float g_ax  [Bb*Nn*CSTR];
__device__ float g_cand[Bb*Nn*CSTR];
__device__ float g_axc [Bb*Nn*CSTR];
__device__ float g_Wg0 [Nn*COG];
__device__ float g_Wg1 [Nn*COG];
__device__ float g_Wu0 [Nn*COU];
__device__ float g_Wu1 [Nn*COU];
__device__ float g_bg  [Nn*OGg];
__device__ float g_bu  [Nn*OUu];
__device__ float g_r   [Bb*Nn*OUu];

__device__ __forceinline__ float sigm(float v){ return 1.f/(1.f+__expf(-v)); }

// ---- tf32 mma.sync helpers (base-PTX only) ----
__device__ __forceinline__ uint32_t tf32u(float v){
    uint32_t o; asm("cvt.rna.tf32.f32 %0, %1;" : "=r"(o) : "f"(v)); return o;
}
__device__ __forceinline__ void mma8(float* c, const uint32_t* a, const uint32_t* b){
    asm volatile("mma.sync.aligned.m16n8k8.row.col.f32.tf32.tf32.f32 "
        "{%0,%1,%2,%3}, {%4,%5,%6,%7}, {%8,%9}, {%0,%1,%2,%3};"
        : "+f"(c[0]), "+f"(c[1]), "+f"(c[2]), "+f"(c[3])
        : "r"(a[0]), "r"(a[1]), "r"(a[2]), "r"(a[3]), "r"(b[0]), "r"(b[1]));
}

// ---------------- K1: build ins (col79=1), tiny MLPs -> p,q ----
__global__ __launch_bounds__(128) void k_prep(
    const float* __restrict__ x, const float* __restrict__ st,
    const float* __restrict__ ne0, const float* __restrict__ ne1,
    const float* __restrict__ w11, const float* __restrict__ b11,
    const float* __restrict__ w12, const float* __restrict__ b12,
    const float* __restrict__ w13, const float* __restrict__ b13,
    const float* __restrict__ w21, const float* __restrict__ b21,
    const float* __restrict__ w22, const float* __restrict__ b22,
    const float* __restrict__ w23, const float* __restrict__ b23)
{
    __shared__ float sw11[1056], sw21[1056];
    __shared__ float sb11[16], sb21[16];
    __shared__ float sw12[32], sw22[32], sb12[2], sb22[2];
    __shared__ float sw13[64], sw23[64], sb13[32], sb23[32];
    __shared__ float sv[128*67];

    int t = threadIdx.x;
    for (int i = t; i < 1056; i += 128){ sw11[i] = w11[i]; sw21[i] = w21[i]; }
    if (t < 16){ sb11[t] = b11[t]; sb21[t] = b21[t]; }
    if (t < 32){
        sw12[t] = w12[t]; sw22[t] = w22[t];
        sw13[t] = w13[t]; sw23[t] = w23[t];
        sw13[32+t] = w13[32+t]; sw23[32+t] = w23[32+t];
        sb13[t] = b13[t]; sb23[t] = b23[t];
    }
    if (t < 2){ sb12[t] = b12[t]; sb22[t] = b22[t]; }

    int idx0 = blockIdx.x*128;
    for (int e = t; e < 256; e += 128){
        int r = e >> 1, c = e & 1;
        float v = x[idx0*2 + e];
        sv[r*67 + c] = v;
        g_ins[(size_t)(idx0+r)*CSTR + c] = v;
    }
    for (int e = t; e < 128*64; e += 128){
        int r = e >> 6, c = e & 63;
        float v = st[(size_t)idx0*64 + e];
        sv[r*67 + 2 + c] = v;
        g_ins[(size_t)(idx0+r)*CSTR + 2 + c] = v;
    }
    for (int e = t; e < 128*14; e += 128){
        int r = e/14, c = 66 + e%14;
        g_ins[(size_t)(idx0+r)*CSTR + c] = (c == 79) ? 1.f : 0.f;
    }
    __syncthreads();

    int idx = idx0 + t;
    int b = idx >> 10;
    const float* vrow = &sv[t*67];

    {
        float h1[16];
        #pragma unroll
        for (int j = 0; j < 16; j++){
            float a = sb11[j];
            for (int i = 0; i < 66; i++) a += vrow[i]*sw11[i*16+j];
            h1[j] = sigm(a);
        }
        float a0 = sb12[0], a1 = sb12[1];
        #pragma unroll
        for (int j = 0; j < 16; j++){ a0 += h1[j]*sw12[j*2]; a1 += h1[j]*sw12[j*2+1]; }
        float h2a = sigm(a0), h2b = sigm(a1);
        #pragma unroll
        for (int o = 0; o < 32; o++){
            float f = sb13[o] + h2a*sw13[o] + h2b*sw13[32+o];
            float nv = tanhf(ne0[b*TDd + o]*f);
            g_p[(size_t)idx*64 + o] = nv;
            g_q[(size_t)idx*64 + 32 + o] = nv;
        }
    }
    {
        float h1[16];
        #pragma unroll
        for (int j = 0; j < 16; j++){
            float a = sb21[j];
            for (int i = 0; i < 66; i++) a += vrow[i]*sw21[i*16+j];
            h1[j] = sigm(a);
        }
        float a0 = sb22[0], a1 = sb22[1];
        #pragma unroll
        for (int j = 0; j < 16; j++){ a0 += h1[j]*sw22[j*2]; a1 += h1[j]*sw22[j*2+1]; }
        float h2a = sigm(a0), h2b = sigm(a1);
        #pragma unroll
        for (int o = 0; o < 32; o++){
            float f = sb23[o] + h2a*sw23[o] + h2b*sw23[32+o];
            float nv = tanhf(ne1[b*TDd + o]*f);
            g_p[(size_t)idx*64 + 32 + o] = -nv;
            g_q[(size_t)idx*64 + o] = nv;
        }
    }
}

// ---------------- K2: effective per-node weights ----------------
template<int CO, bool GATE>
__global__ __launch_bounds__(128) void k_wmix(const float* __restrict__ pool,
                                              const float* __restrict__ ne2)
{
    __shared__ float sne[64*EDd];
    int t = threadIdx.x;
    int row0 = blockIdx.y*64;
    for (int i = t; i < 64*EDd; i += 128) sne[i] = ne2[row0*EDd + i];
    __syncthreads();

    int col = blockIdx.x*128 + t;
    float ga[EDd], gb[EDd];
    #pragma unroll
    for (int d = 0; d < EDd; d++){
        ga[d] = pool[(size_t)(d*4+0)*CO + col] + pool[(size_t)(d*4+2)*CO + col];
        gb[d] = pool[(size_t)(d*4+1)*CO + col] + pool[(size_t)(d*4+3)*CO + col];
    }
    float* o0 = GATE ? g_Wg0 : g_Wu0;
    float* o1 = GATE ? g_Wg1 : g_Wu1;
    for (int r = 0; r < 64; r++){
        float a0 = 0.f, a1 = 0.f;
        #pragma unroll
        for (int d = 0; d < EDd; d++){ float e = sne[r*EDd+d]; a0 += e*ga[d]; a1 += e*gb[d]; }
        o0[(size_t)(row0+r)*CO + col] = a0;
        o1[(size_t)(row0+r)*CO + col] = a1;
    }
}

__global__ void k_biases(const float* __restrict__ bg_pool, const float* __restrict__ bu_pool,
                         const float* __restrict__ ne2)
{
    int n = blockIdx.x, t = threadIdx.x;
    float ne[EDd];
    #pragma unroll
    for (int d = 0; d < EDd; d++) ne[d] = ne2[n*EDd+d];
    if (t < 128){
        float a = 0.f;
        #pragma unroll
        for (int d = 0; d < EDd; d++) a += ne[d]*bg_pool[d*OGg+t];
        g_bg[n*OGg + t] = a;
    } else {
        int o = t - 128;
        float a = 0.f;
        #pragma unroll
        for (int d = 0; d < EDd; d++) a += ne[d]*bu_pool[d*OUu+o];
        g_bu[n*OUu + o] = a;
    }
}

// ---------------- K3: FUSED  Y = (relu(P·Q^T) @ X + X)/rowsum ----------------
// grid (8, Bb), block 256 (8 warps). Row tile 128, col loop 32 chunks of 32.
// Per chunk: adjc[128x32] = relu(P[128x64]·Qc[32x64]^T) (mma, warp w = m16 tile w),
// STS tf32(adjc) -> sAdj, then accY += adjc @ Xc (warp: wg=w>>1 rows wg*32, cg=w&1 cols cg*40).
// smem words: sP[128*68]=8704 @0 | sQ[32*68]=2176 @8704 | sX[32*88]=2816 @10880
//             sAdj[128*36]=4608 @13696 | srs[128] @18304  -> 18432 w = 73728 B
#define FUSED_SMEM 73728
template<bool SECOND>
__global__ __launch_bounds__(256) void k_fused(){
    extern __shared__ uint32_t fsm[];
    uint32_t* sP   = fsm;              // [128][68] : 64 k + 4 pad (stride 68)
    uint32_t* sQ   = fsm + 8704;       // [32][68]
    uint32_t* sX   = fsm + 10880;      // [32][88]
    uint32_t* sAdj = fsm + 13696;      // [128][36] : 32 k + 4 pad
    float*    srs  = (float*)(fsm + 18304);
    const float* X = SECOND ? g_cand : g_ins;
    float*       Y = SECOND ? g_axc  : g_ax;
    int t = threadIdx.x, w = t >> 5, lane = t & 31;
    int wg = w >> 1, cg = w & 1;
    int quad = lane >> 2, tig = lane & 3;
    int b = blockIdx.y;
    int row0 = blockIdx.x*128;
    const float* Pb = g_p + (size_t)b*Nn*64;
    const float* Qb = g_q + (size_t)b*Nn*64;
    const float* Xb = X + (size_t)b*Nn*CSTR;

    // stage P rows once (tf32), stride 68
    #pragma unroll
    for (int p = 0; p < 8; p++){
        int e = t + p*256;              // 2048 float4
        int r = e >> 4, m = e & 15;
        float4 v = *(const float4*)&Pb[(size_t)(row0+r)*64 + m*4];
        uint4 u;
        u.x = tf32u(v.x); u.y = tf32u(v.y); u.z = tf32u(v.z); u.w = tf32u(v.w);
        *(uint4*)&sP[r*68 + m*4] = u;
    }

    float accY[2][5][4] = {};

    for (int kc = 0; kc < 32; kc++){
        __syncthreads();    // prior chunk done reading sQ/sX/sAdj (and 1st iter: sP staged)
        // stage Q chunk: adj cols kc*32..+32 -> rows of q, stride 68
        #pragma unroll
        for (int p = 0; p < 2; p++){
            int e = t + p*256;          // 512 float4
            int c = e >> 4, m = e & 15;
            float4 v = *(const float4*)&Qb[(size_t)(kc*32+c)*64 + m*4];
            uint4 u;
            u.x = tf32u(v.x); u.y = tf32u(v.y); u.z = tf32u(v.z); u.w = tf32u(v.w);
            *(uint4*)&sQ[c*68 + m*4] = u;
        }
        // stage X chunk: 32(k) x 80(n)
        #pragma unroll
        for (int p = 0; p < 10; p++){
            int e = t + p*256;          // 2560
            int k = e/80, n = e%80;
            sX[k*88 + n] = tf32u(Xb[(size_t)(kc*32 + k)*CSTR + n]);
        }
        __syncthreads();

        // adj mma: warp w handles m16 tile w (rows w*16..+16), all 4 n8 tiles, K=64
        float accA[4][4] = {};
        #pragma unroll
        for (int k8 = 0; k8 < 8; k8++){
            int kk = k8*8;
            uint32_t a[4];
            int R = w*16 + quad;
            a[0] = sP[(R  )*68 + kk + tig];
            a[1] = sP[(R+8)*68 + kk + tig];
            a[2] = sP[(R  )*68 + kk + tig + 4];
            a[3] = sP[(R+8)*68 + kk + tig + 4];
            #pragma unroll
            for (int nj = 0; nj < 4; nj++){
                int n = nj*8 + quad;
                uint32_t bq[2];
                bq[0] = sQ[n*68 + kk + tig];
                bq[1] = sQ[n*68 + kk + tig + 4];
                mma8(accA[nj], a, bq);
            }
        }
        // relu + tf32 + STS to sAdj [row][k] stride 36
        {
            int R = w*16 + quad;
            #pragma unroll
            for (int nj = 0; nj < 4; nj++){
                uint2 u0, u1;
                u0.x = tf32u(fmaxf(accA[nj][0], 0.f));
                u0.y = tf32u(fmaxf(accA[nj][1], 0.f));
                u1.x = tf32u(fmaxf(accA[nj][2], 0.f));
                u1.y = tf32u(fmaxf(accA[nj][3], 0.f));
                *(uint2*)&sAdj[(R  )*36 + nj*8 + 2*tig] = u0;
                *(uint2*)&sAdj[(R+8)*36 + nj*8 + 2*tig] = u1;
            }
        }
        __syncthreads();

        // spmm mma: accY += adjc @ Xc
        #pragma unroll
        for (int k8 = 0; k8 < 4; k8++){
            int kk = k8*8;
            uint32_t a[2][4];
            #pragma unroll
            for (int mi = 0; mi < 2; mi++){
                int R = wg*32 + mi*16 + quad;
                a[mi][0] = sAdj[(R  )*36 + kk + tig];
                a[mi][1] = sAdj[(R+8)*36 + kk + tig];
                a[mi][2] = sAdj[(R  )*36 + kk + tig + 4];
                a[mi][3] = sAdj[(R+8)*36 + kk + tig + 4];
            }
            #pragma unroll
            for (int nj = 0; nj < 5; nj++){
                int n = cg*40 + nj*8 + quad;
                uint32_t bf[2];
                bf[0] = sX[(kk + tig    )*88 + n];
                bf[1] = sX[(kk + tig + 4)*88 + n];
                mma8(accY[0][nj], a[0], bf);
                mma8(accY[1][nj], a[1], bf);
            }
        }
    }

    // rowsum from ones-col 79: cg==1, nj==4, tig==3 -> c1/c3 = col 79
    if (cg == 1 && tig == 3){
        #pragma unroll
        for (int mi = 0; mi < 2; mi++){
            srs[wg*32 + mi*16 + quad    ] = accY[mi][4][1] + 1.f;
            srs[wg*32 + mi*16 + quad + 8] = accY[mi][4][3] + 1.f;
        }
    }
    __syncthreads();

    #pragma unroll
    for (int mi = 0; mi < 2; mi++){
        #pragma unroll
        for (int rp = 0; rp < 2; rp++){
            int lr  = wg*32 + mi*16 + quad + rp*8;
            int row = row0 + lr;
            float inv = 1.f/srs[lr];
            const float* xr = Xb + (size_t)row*CSTR;
            float* yr = Y + ((size_t)b*Nn + row)*CSTR;
            #pragma unroll
            for (int nj = 0; nj < 5; nj++){
                int col = cg*40 + nj*8 + 2*tig;
                float2 xv = *(const float2*)&xr[col];
                float2 o;
                o.x = (accY[mi][nj][rp*2+0] + xv.x)*inv;
                o.y = (accY[mi][nj][rp*2+1] + xv.y)*inv;
                *(float2*)&yr[col] = o;
            }
        }
    }
}

// ---------------- K5: gate node-GEMM -> z,r; builds cand (col79=1) ----------------
__global__ __launch_bounds__(128) void k_gate(const float* __restrict__ x,
                                              const float* __restrict__ state)
{
    extern __shared__ float sm[];
    float* sW0 = sm;
    float* sW1 = sm + COG;
    float* sX  = sm + 2*COG;
    float* sAX = sm + 2*COG + 2112;
    int n = blockIdx.x, t = threadIdx.x;
    int bg = t >> 5, og = t & 31;

    {
        float4* d0 = (float4*)sW0; const float4* s0 = (const float4*)(g_Wg0 + (size_t)n*COG);
        float4* d1 = (float4*)sW1; const float4* s1 = (const float4*)(g_Wg1 + (size_t)n*COG);
        for (int e = t; e < COG/4; e += 128){ d0[e] = s0[e]; d1[e] = s1[e]; }
    }
    for (int e = t; e < 32*66; e += 128){
        int bi = e/66, i = e%66;
        sX [e] = g_ins[((size_t)bi*Nn + n)*CSTR + i];
        sAX[e] = g_ax [((size_t)bi*Nn + n)*CSTR + i];
    }
    __syncthreads();

    float4 acc[8] = {};
    #pragma unroll 2
    for (int i = 0; i < 66; i++){
        float4 w0 = ((const float4*)sW0)[i*32 + og];
        float4 w1 = ((const float4*)sW1)[i*32 + og];
        #pragma unroll
        for (int bb = 0; bb < 8; bb++){
            int bi = bg*8 + bb;
            float xv = sX[bi*66 + i], av = sAX[bi*66 + i];
            acc[bb].x += xv*w0.x + av*w1.x;
            acc[bb].y += xv*w0.y + av*w1.y;
            acc[bb].z += xv*w0.z + av*w1.z;
            acc[bb].w += xv*w0.w + av*w1.w;
        }
    }
    float4 bias = *(const float4*)(g_bg + n*OGg + og*4);
    int o0 = og*4;
    #pragma unroll
    for (int bb = 0; bb < 8; bb++){
        int bi = bg*8 + bb;
        size_t bn = (size_t)bi*Nn + n;
        float vals[4] = { acc[bb].x + bias.x, acc[bb].y + bias.y,
                          acc[bb].z + bias.z, acc[bb].w + bias.w };
        #pragma unroll
        for (int c = 0; c < 4; c++){
            float zz = sigm(vals[c]);
            int o = o0 + c;
            if (o < 64) g_cand[bn*CSTR + 2 + o] = zz * state[bn*64 + o];
            else        g_r  [bn*64 + (o - 64)] = zz;
        }
    }
    if (og == 0){
        #pragma unroll
        for (int bb = 0; bb < 8; bb++){
            size_t bn = (size_t)(bg*8 + bb)*Nn + n;
            g_cand[bn*CSTR + 0] = x[bn*2 + 0];
            g_cand[bn*CSTR + 1] = x[bn*2 + 1];
            #pragma unroll
            for (int c = 66; c < 80; c++) g_cand[bn*CSTR + c] = (c == 79) ? 1.f : 0.f;
        }
    }
}

// ---------------- K8: upd node-GEMM -> hc; final out ----------------
__global__ __launch_bounds__(128) void k_upd(const float* __restrict__ state,
                                             float* __restrict__ out)
{
    extern __shared__ float sm[];
    float* sW0 = sm;
    float* sW1 = sm + COU;
    float* sX  = sm + 2*COU;
    float* sAX = sm + 2*COU + 2112;
    int n = blockIdx.x, t = threadIdx.x;
    int bg = t >> 5, og = t & 31;

    {
        float4* d0 = (float4*)sW0; const float4* s0 = (const float4*)(g_Wu0 + (size_t)n*COU);
        float4* d1 = (float4*)sW1; const float4* s1 = (const float4*)(g_Wu1 + (size_t)n*COU);
        for (int e = t; e < COU/4; e += 128){ d0[e] = s0[e]; d1[e] = s1[e]; }
    }
    for (int e = t; e < 32*66; e += 128){
        int bi = e/66, i = e%66;
        sX [e] = g_cand[((size_t)bi*Nn + n)*CSTR + i];
        sAX[e] = g_axc [((size_t)bi*Nn + n)*CSTR + i];
    }
    __syncthreads();

    float2 acc[8] = {};
    #pragma unroll 2
    for (int i = 0; i < 66; i++){
        float2 w0 = ((const float2*)sW0)[i*32 + og];
        float2 w1 = ((const float2*)sW1)[i*32 + og];
        #pragma unroll
        for (int bb = 0; bb < 8; bb++){
            int bi = bg*8 + bb;
            float xv = sX[bi*66 + i], av = sAX[bi*66 + i];
            acc[bb].x += xv*w0.x + av*w1.x;
            acc[bb].y += xv*w0.y + av*w1.y;
        }
    }
    float2 bias = ((const float2*)(g_bu + n*OUu))[og];
    #pragma unroll
    for (int bb = 0; bb < 8; bb++){
        int bi = bg*8 + bb;
        size_t bn = (size_t)bi*Nn + n;
        #pragma unroll
        for (int c = 0; c < 2; c++){
            int o = og*2 + c;
            float hc = tanhf((c ? acc[bb].y + bias.y : acc[bb].x + bias.x));
            float rr = g_r[bn*64 + o];
            float sv = state[bn*64 + o];
            out[bn*64 + o] = rr*sv + (1.f - rr)*hc;
        }
    }
}

// ---------------- launcher ----------------
extern "C" void kernel_launch(void* const* d_in, const int* in_sizes, int n_in,
                              void* d_out, int out_size)
{
    const float* x      = (const float*)d_in[0];
    const float* state  = (const float*)d_in[1];
    const float* ne0    = (const float*)d_in[2];
    const float* ne1    = (const float*)d_in[3];
    const float* ne2    = (const float*)d_in[4];
    const float* f1w1   = (const float*)d_in[5];
    const float* f1b1   = (const float*)d_in[6];
    const float* f1w2   = (const float*)d_in[7];
    const float* f1b2   = (const float*)d_in[8];
    const float* f1w3   = (const float*)d_in[9];
    const float* f1b3   = (const float*)d_in[10];
    const float* f2w1   = (const float*)d_in[11];
    const float* f2b1   = (const float*)d_in[12];
    const float* f2w2   = (const float*)d_in[13];
    const float* f2b2   = (const float*)d_in[14];
    const float* f2w3   = (const float*)d_in[15];
    const float* f2b3   = (const float*)d_in[16];
    const float* gate_w = (const float*)d_in[17];
    const float* gate_b = (const float*)d_in[18];
    const float* upd_w  = (const float*)d_in[19];
    const float* upd_b  = (const float*)d_in[20];
    float* out = (float*)d_out;

    cudaFuncSetAttribute(k_fused<false>, cudaFuncAttributeMaxDynamicSharedMemorySize, FUSED_SMEM);
    cudaFuncSetAttribute(k_fused<true>,  cudaFuncAttributeMaxDynamicSharedMemorySize, FUSED_SMEM);
    cudaFuncSetAttribute(k_gate, cudaFuncAttributeMaxDynamicSharedMemorySize, (2*COG + 2*2112)*4);
    cudaFuncSetAttribute(k_upd,  cudaFuncAttributeMaxDynamicSharedMemorySize, (2*COU + 2*2112)*4);

    // Launch #4 (the one ncu captures) = k_fused<false>.
    k_prep<<<256, 128>>>(x, state, ne0, ne1,
                         f1w1, f1b1, f1w2, f1b2, f1w3, f1b3,
                         f2w1, f2b1, f2w2, f2b2, f2w3, f2b3);
    k_wmix<COG, true ><<<dim3(COG/128, Nn/64), 128>>>(gate_w, ne2);
    k_wmix<COU, false><<<dim3(COU/128, Nn/64), 128>>>(upd_w,  ne2);
    k_fused<false><<<dim3(8, Bb), 256, FUSED_SMEM>>>();
    k_biases<<<Nn, 192>>>(gate_b, upd_b, ne2);
    k_gate<<<Nn, 128, (2*COG + 2*2112)*4>>>(x, state);
    k_fused<true><<<dim3(8, Bb), 256, FUSED_SMEM>>>();
    k_upd<<<Nn, 128, (2*COU + 2*2112)*4>>>(state, out);
}